// round 1
// baseline (speedup 1.0000x reference)
#include <cuda_runtime.h>

#define NT 32
#define NQ 256
#define NNODE 8192
#define DD 128
#define CHN 32
#define KK 16
#define NBF 8
#define BB 4
#define CAP 4096

__device__ float g_nfext[NNODE * DD];     // node_feature @ W_ext
__device__ float g_tf[DD];                // 1 + time_emb @ W_time
__device__ int   g_range[BB + 1];         // batch ranges in sorted node_batch
__device__ float g_coef[6 * CHN];         // folded dtp coefs: lin(a,b,e), ang(a,b,e)
__device__ float g_partial[NT * NQ * 6];  // per-(t,q) partials: ang3, lin3

static __device__ __forceinline__ unsigned long long umin64(unsigned long long a, unsigned long long b) {
    return a < b ? a : b;
}

static __device__ __forceinline__ float3 qrot(float w, float x, float y, float z, float3 v) {
    // v + 2*(w*(u x v) + u x (u x v)), u=(x,y,z)
    float uvx = y * v.z - z * v.y;
    float uvy = z * v.x - x * v.z;
    float uvz = x * v.y - y * v.x;
    float wx = y * uvz - z * uvy;
    float wy = z * uvx - x * uvz;
    float wz = x * uvy - y * uvx;
    float3 r;
    r.x = v.x + 2.f * (w * uvx + wx);
    r.y = v.y + 2.f * (w * uvy + wy);
    r.z = v.z + 2.f * (w * uvz + wz);
    return r;
}

// ---- precompute nf_ext = node_feature @ W_ext --------------------------------
__global__ void k_nfext(const float* __restrict__ nf, const float* __restrict__ Wext) {
    __shared__ float s[DD];
    int n = blockIdx.x, tid = threadIdx.x;
    s[tid] = nf[n * DD + tid];
    __syncthreads();
    float acc = 0.f;
#pragma unroll 8
    for (int k = 0; k < DD; k++) acc = fmaf(s[k], Wext[k * DD + tid], acc);
    g_nfext[n * DD + tid] = acc;
}

// ---- precompute tf, batch ranges, folded dtp coefs ---------------------------
__global__ void k_misc(const float* __restrict__ te, const float* __restrict__ Wtime,
                       const int* __restrict__ nbatch,
                       const float* __restrict__ wp_lin, const float* __restrict__ Wv_lin,
                       const float* __restrict__ wp_ang, const float* __restrict__ Wv_ang) {
    int tid = threadIdx.x;  // 192 threads
    if (tid < DD) {
        float acc = 0.f;
        for (int k = 0; k < DD; k++) acc = fmaf(te[k], Wtime[k * DD + tid], acc);
        g_tf[tid] = 1.f + acc;
    }
    if (tid <= BB) {
        int lo = 0, hi = NNODE;
        if (tid == BB) lo = NNODE;
        else {
            while (lo < hi) { int m = (lo + hi) >> 1; if (nbatch[m] < tid) lo = m + 1; else hi = m; }
        }
        g_range[tid] = lo;
    }
    {
        int g = tid / CHN, c = tid % CHN;  // g in 0..5
        const float* wp = (g < 3) ? wp_lin : wp_ang;
        const float* Wv = (g < 3) ? Wv_lin : Wv_ang;
        int gg = g % 3;                    // 0=su, 1=vt, 2=cross
        int wrow = gg * CHN + c;
        float s = 0.f;
        for (int o = 0; o < CHN; o++) s += Wv[wrow * CHN + o];
        s *= (1.f / (float)CHN);           // fold mean over output channels
        g_coef[g * CHN + c] = wp[(2 + gg) * CHN + c] * s;
    }
}

// ---- main: one block per (query, transform) ----------------------------------
__global__ __launch_bounds__(256) void k_main(
    const float* __restrict__ T, const float* __restrict__ qwgt,
    const float* __restrict__ qf, const float* __restrict__ qcrd,
    const float* __restrict__ ncoord, const float* __restrict__ Wrbf,
    const int* __restrict__ qbatch) {
    __shared__ float sd2[CAP];
    __shared__ unsigned long long stmin[256];
    __shared__ unsigned long long swmin[8];
    __shared__ unsigned long long ssel[KK];
    __shared__ float srbf[KK][NBF];
    __shared__ float sfield[DD];

    int qi = blockIdx.x, t = blockIdx.y, tid = threadIdx.x;
    int lane = tid & 31, wid = tid >> 5;

    float qw0 = T[t * 7 + 0], qx = T[t * 7 + 1], qy = T[t * 7 + 2], qz = T[t * 7 + 3];
    float3 X = { T[t * 7 + 4], T[t * 7 + 5], T[t * 7 + 6] };
    float3 qc0 = { qcrd[qi * 3 + 0], qcrd[qi * 3 + 1], qcrd[qi * 3 + 2] };
    float3 p = qrot(qw0, qx, qy, qz, qc0);
    p.x += X.x; p.y += X.y; p.z += X.z;

    int b = qbatch[qi];
    int lo = g_range[b];
    int n = g_range[b + 1] - lo;
    if (n > CAP) n = CAP;

    // distances + per-thread running min (key = d2 bits | local pos)
    unsigned long long m = ~0ull;
    for (int i = tid; i < n; i += 256) {
        float dx = p.x - ncoord[(lo + i) * 3 + 0];
        float dy = p.y - ncoord[(lo + i) * 3 + 1];
        float dz = p.z - ncoord[(lo + i) * 3 + 2];
        float d2 = dx * dx + dy * dy + dz * dz;
        sd2[i] = d2;
        unsigned long long key = ((unsigned long long)__float_as_uint(d2) << 32) | (unsigned)i;
        m = umin64(m, key);
    }
    stmin[tid] = m;
    __syncthreads();

    // extract top-KK smallest via cached per-thread minima
    for (int k = 0; k < KK; k++) {
        unsigned long long v = stmin[tid];
#pragma unroll
        for (int o = 16; o > 0; o >>= 1)
            v = umin64(v, __shfl_down_sync(0xffffffffu, v, o));
        if (lane == 0) swmin[wid] = v;
        __syncthreads();
        if (tid < 8) {
            unsigned long long v2 = swmin[tid];
#pragma unroll
            for (int o = 4; o > 0; o >>= 1)
                v2 = umin64(v2, __shfl_down_sync(0xffu, v2, o));
            if (tid == 0) ssel[k] = v2;
        }
        __syncthreads();
        unsigned pos = (unsigned)ssel[k];
        if ((pos & 255u) == (unsigned)tid) {
            sd2[pos] = __int_as_float(0x7f800000);  // +inf: remove from pool
            unsigned long long mm = ~0ull;
            for (int i = tid; i < n; i += 256) {
                unsigned long long key = ((unsigned long long)__float_as_uint(sd2[i]) << 32) | (unsigned)i;
                mm = umin64(mm, key);
            }
            stmin[tid] = mm;
        }
        __syncthreads();
    }

    // rbf basis for the 16 selected
    if (tid < KK * NBF) {
        int k = tid >> 3, bb = tid & 7;
        float d2 = __uint_as_float((unsigned)(ssel[k] >> 32));
        float d = sqrtf(fmaxf(d2, 1e-12f));
        float c = (3.0f / 7.0f) * (float)bb;
        float e = d - c;
        srbf[k][bb] = expf(-4.f * e * e);
    }
    __syncthreads();

    // field[d] = tf[d] * sum_k (rbf[k] @ W_rbf)[d] * nf_ext[idx_k][d]
    if (tid < DD) {
        float acc = 0.f;
#pragma unroll
        for (int k = 0; k < KK; k++) {
            int gi = lo + (int)(unsigned)ssel[k];
            float coef = 0.f;
#pragma unroll
            for (int bb2 = 0; bb2 < NBF; bb2++)
                coef = fmaf(srbf[k][bb2], Wrbf[bb2 * DD + tid], coef);
            acc = fmaf(coef, g_nfext[gi * DD + tid], acc);
        }
        sfield[tid] = acc * g_tf[tid];
    }
    __syncthreads();

    // dtp + epilogue on warp 0 (c = lane)
    if (tid < CHN) {
        int c = tid;
        float s = qf[qi * DD + c];
        float3 v0 = { qf[qi * DD + CHN + 3 * c + 0], qf[qi * DD + CHN + 3 * c + 1], qf[qi * DD + CHN + 3 * c + 2] };
        float3 v = qrot(qw0, qx, qy, qz, v0);
        float tt = sfield[c];
        float3 u = { sfield[CHN + 3 * c + 0], sfield[CHN + 3 * c + 1], sfield[CHN + 3 * c + 2] };
        float3 cr = { v.y * u.z - v.z * u.y, v.z * u.x - v.x * u.z, v.x * u.y - v.y * u.x };
        float al = g_coef[c], bl = g_coef[CHN + c], el = g_coef[2 * CHN + c];
        float aa = g_coef[3 * CHN + c], ba = g_coef[4 * CHN + c], ea = g_coef[5 * CHN + c];
        float lvx = al * s * u.x + bl * tt * v.x + el * cr.x;
        float lvy = al * s * u.y + bl * tt * v.y + el * cr.y;
        float lvz = al * s * u.z + bl * tt * v.z + el * cr.z;
        float avx = aa * s * u.x + ba * tt * v.x + ea * cr.x;
        float avy = aa * s * u.y + ba * tt * v.y + ea * cr.y;
        float avz = aa * s * u.z + ba * tt * v.z + ea * cr.z;
#pragma unroll
        for (int o = 16; o > 0; o >>= 1) {
            lvx += __shfl_down_sync(0xffffffffu, lvx, o);
            lvy += __shfl_down_sync(0xffffffffu, lvy, o);
            lvz += __shfl_down_sync(0xffffffffu, lvz, o);
            avx += __shfl_down_sync(0xffffffffu, avx, o);
            avy += __shfl_down_sync(0xffffffffu, avy, o);
            avz += __shfl_down_sync(0xffffffffu, avz, o);
        }
        if (c == 0) {
            float3 lv = qrot(qw0, -qx, -qy, -qz, make_float3(lvx, lvy, lvz));
            float3 av = qrot(qw0, -qx, -qy, -qz, make_float3(avx, avy, avz));
            float3 orb = { qc0.y * lv.z - qc0.z * lv.y,
                           qc0.z * lv.x - qc0.x * lv.z,
                           qc0.x * lv.y - qc0.y * lv.x };
            float w = qwgt[qi];
            const float inv_s2 = 0.70710678118654752440f;  // 1/ANG_MULT
            float* pp = &g_partial[(t * NQ + qi) * 6];
            pp[0] = w * (orb.x + av.x * inv_s2);
            pp[1] = w * (orb.y + av.y * inv_s2);
            pp[2] = w * (orb.z + av.z * inv_s2);
            pp[3] = w * lv.x;
            pp[4] = w * lv.y;
            pp[5] = w * lv.z;
        }
    }
}

// ---- deterministic final reduction over queries ------------------------------
__global__ void k_reduce(float* __restrict__ out) {
    int t = blockIdx.x, tid = threadIdx.x;  // 256 threads
    int lane = tid & 31, wid = tid >> 5;
    float a[6];
    const float* pp = &g_partial[(t * NQ + tid) * 6];
#pragma unroll
    for (int j = 0; j < 6; j++) a[j] = pp[j];
#pragma unroll
    for (int j = 0; j < 6; j++) {
        for (int o = 16; o > 0; o >>= 1)
            a[j] += __shfl_down_sync(0xffffffffu, a[j], o);
    }
    __shared__ float sw[8][6];
    if (lane == 0) {
#pragma unroll
        for (int j = 0; j < 6; j++) sw[wid][j] = a[j];
    }
    __syncthreads();
    if (tid == 0) {
        float r[6] = {0, 0, 0, 0, 0, 0};
        for (int w2 = 0; w2 < 8; w2++)
            for (int j = 0; j < 6; j++) r[j] += sw[w2][j];
        // output: ang_out (32,3) then lin_out (32,3)
        out[t * 3 + 0] = r[0];
        out[t * 3 + 1] = r[1];
        out[t * 3 + 2] = r[2];
        out[NT * 3 + t * 3 + 0] = r[3];
        out[NT * 3 + t * 3 + 1] = r[4];
        out[NT * 3 + t * 3 + 2] = r[5];
    }
}

extern "C" void kernel_launch(void* const* d_in, const int* in_sizes, int n_in,
                              void* d_out, int out_size) {
    const float* T      = (const float*)d_in[0];
    const float* qwgt   = (const float*)d_in[1];
    const float* qfeat  = (const float*)d_in[2];
    const float* qcoord = (const float*)d_in[3];
    const float* nfeat  = (const float*)d_in[4];
    const float* ncoord = (const float*)d_in[5];
    const float* temb   = (const float*)d_in[6];
    const float* Wext   = (const float*)d_in[7];
    const float* Wrbf   = (const float*)d_in[8];
    const float* Wtime  = (const float*)d_in[9];
    const float* wp_lin = (const float*)d_in[10];
    const float* Wv_lin = (const float*)d_in[12];
    const float* wp_ang = (const float*)d_in[13];
    const float* Wv_ang = (const float*)d_in[15];
    const int*   qbatch = (const int*)d_in[16];
    const int*   nbatch = (const int*)d_in[17];
    float* out = (float*)d_out;

    k_nfext<<<NNODE, DD>>>(nfeat, Wext);
    k_misc<<<1, 192>>>(temb, Wtime, nbatch, wp_lin, Wv_lin, wp_ang, Wv_ang);
    k_main<<<dim3(NQ, NT), 256>>>(T, qwgt, qfeat, qcoord, ncoord, Wrbf, qbatch);
    k_reduce<<<NT, NQ>>>(out);
}